// round 1
// baseline (speedup 1.0000x reference)
#include <cuda_runtime.h>
#include <cuda_bf16.h>
#include <math.h>

// ---------------------------------------------------------------------------
// Problem constants
// ---------------------------------------------------------------------------
#define B_SZ   4
#define T_SZ   2048
#define DIM    2048
#define NH     16
#define NKV    4
#define HD     128

// ---------------------------------------------------------------------------
// Device scratch (allocation-free rule: __device__ globals)
// ---------------------------------------------------------------------------
__device__ float g_q[(size_t)B_SZ * NH  * T_SZ * HD];   // [b,h,t,d]  64 MB
__device__ float g_k[(size_t)B_SZ * NKV * T_SZ * HD];   // [b,h,t,d]  16 MB
__device__ float g_v[(size_t)B_SZ * NKV * T_SZ * HD];   // [b,h,t,d]  16 MB
__device__ float g_attn[(size_t)B_SZ * T_SZ * NH * HD]; // [b,t,h*d]  64 MB

// ---------------------------------------------------------------------------
// NT GEMM:  C[m,n] = sum_k A[m,k] * B[n,k]
// Tile 128x128x16, 256 threads, 8x8 frags.
// mode 0: C row-major [M,N]
// mode 1: C scattered to [b, h, t, d] head layout (H heads, HD=128)
// ---------------------------------------------------------------------------
__global__ __launch_bounds__(256) void sgemm_nt(
    const float* __restrict__ A, const float* __restrict__ Bw,
    float* __restrict__ C, int M, int N, int K, int mode, int H)
{
    __shared__ float As[16][128];
    __shared__ float Bs[16][128];

    const int tid = threadIdx.x;
    const int tx  = tid & 15;
    const int ty  = tid >> 4;
    const int bm  = blockIdx.y * 128;
    const int bn  = blockIdx.x * 128;

    const float* Ab = A  + (size_t)bm * K;
    const float* Bb = Bw + (size_t)bn * K;

    float acc[8][8];
#pragma unroll
    for (int i = 0; i < 8; i++)
#pragma unroll
        for (int j = 0; j < 8; j++) acc[i][j] = 0.0f;

    for (int k0 = 0; k0 < K; k0 += 16) {
#pragma unroll
        for (int l = 0; l < 2; l++) {
            int lin = tid + l * 256;          // 0..511 float4 slots
            int row = lin >> 2;               // 0..127
            int c   = (lin & 3) << 2;         // 0,4,8,12
            float4 av = *(const float4*)(Ab + (size_t)row * K + k0 + c);
            As[c + 0][row] = av.x; As[c + 1][row] = av.y;
            As[c + 2][row] = av.z; As[c + 3][row] = av.w;
            float4 bv = *(const float4*)(Bb + (size_t)row * K + k0 + c);
            Bs[c + 0][row] = bv.x; Bs[c + 1][row] = bv.y;
            Bs[c + 2][row] = bv.z; Bs[c + 3][row] = bv.w;
        }
        __syncthreads();

#pragma unroll
        for (int kk = 0; kk < 16; kk++) {
            float a[8], b[8];
            *(float4*)&a[0] = *(const float4*)&As[kk][ty * 8];
            *(float4*)&a[4] = *(const float4*)&As[kk][ty * 8 + 4];
            *(float4*)&b[0] = *(const float4*)&Bs[kk][tx * 8];
            *(float4*)&b[4] = *(const float4*)&Bs[kk][tx * 8 + 4];
#pragma unroll
            for (int i = 0; i < 8; i++)
#pragma unroll
                for (int j = 0; j < 8; j++)
                    acc[i][j] = fmaf(a[i], b[j], acc[i][j]);
        }
        __syncthreads();
    }

    if (mode == 0) {
#pragma unroll
        for (int i = 0; i < 8; i++) {
            int row = bm + ty * 8 + i;
            float* cp = C + (size_t)row * N + bn + tx * 8;
            float4 v0 = make_float4(acc[i][0], acc[i][1], acc[i][2], acc[i][3]);
            float4 v1 = make_float4(acc[i][4], acc[i][5], acc[i][6], acc[i][7]);
            *(float4*)cp       = v0;
            *(float4*)(cp + 4) = v1;
        }
    } else {
        // n = bn + tx*8 + j  ->  h = bn/128 (constant per block), d = tx*8+j
        // m = bm + ty*8 + i  ->  b = bm/2048 (constant per block), t = (bm&2047)+ty*8+i
        const int h     = bn >> 7;
        const int b     = bm >> 11;
        const int tbase = bm & (T_SZ - 1);
#pragma unroll
        for (int i = 0; i < 8; i++) {
            int t = tbase + ty * 8 + i;
            float* cp = C + (((size_t)(b * H + h) * T_SZ + t) * HD) + tx * 8;
            float4 v0 = make_float4(acc[i][0], acc[i][1], acc[i][2], acc[i][3]);
            float4 v1 = make_float4(acc[i][4], acc[i][5], acc[i][6], acc[i][7]);
            *(float4*)cp       = v0;
            *(float4*)(cp + 4) = v1;
        }
    }
}

// ---------------------------------------------------------------------------
// RoPE in-place on [b, h, t, 128] tensors.
// grid = B*nh*T blocks, 64 threads; thread d handles pair (d, d+64).
// ---------------------------------------------------------------------------
__global__ void rope_kernel(float* __restrict__ x,
                            const float* __restrict__ cosb,
                            const float* __restrict__ sinb, int nh)
{
    const int d   = threadIdx.x;          // 0..63
    const int idx = blockIdx.x;           // (b*nh + h)*T + t
    const int t   = idx & (T_SZ - 1);
    const int bh  = idx >> 11;
    const int b   = bh / nh;

    float* p = x + (size_t)idx * HD;
    const float* cp = cosb + ((size_t)b * T_SZ + t) * HD;
    const float* sp = sinb + ((size_t)b * T_SZ + t) * HD;

    float x1 = p[d], x2 = p[d + 64];
    float c1 = cp[d], s1 = sp[d];
    float c2 = cp[d + 64], s2 = sp[d + 64];
    p[d]      = x1 * c1 - x2 * s1;
    p[d + 64] = x2 * c2 + x1 * s2;
}

// ---------------------------------------------------------------------------
// Flash attention, fp32, causal.  One block per (q-tile of 128, head, batch).
// Tiles: 128(q) x 128(kv), D=128.  256 threads; per-thread 8x8 frags with
// row = lane + i*16 striding (conflict-free LDS with pad-129 smem).
// P overwrites the K smem buffer between the two GEMMs.
// ---------------------------------------------------------------------------
#define QS_STRIDE 129
__global__ __launch_bounds__(256, 1) void attn_kernel(
    const float* __restrict__ Qg, const float* __restrict__ Kg,
    const float* __restrict__ Vg, float* __restrict__ Og)
{
    extern __shared__ float sm[];
    float* Qs = sm;                         // 128 x 129
    float* Ks = sm + 128 * QS_STRIDE;       // 128 x 129  (reused as P)
    float* Vs = sm + 2 * 128 * QS_STRIDE;   // 128 x 128  (unpadded, vector loads)

    const int tid = threadIdx.x;
    const int tx  = tid & 15;
    const int ty  = tid >> 4;
    const int qt  = blockIdx.x;     // 0..15
    const int h   = blockIdx.y;     // 0..15
    const int b   = blockIdx.z;     // 0..3
    const int hk  = h >> 2;         // GQA: 4 q heads per kv head

    const float* Qb = Qg + (((size_t)(b * NH  + h ) * T_SZ) + qt * 128) * HD;
    const float* Kb = Kg + ((size_t)(b * NKV + hk) * T_SZ) * HD;
    const float* Vb = Vg + ((size_t)(b * NKV + hk) * T_SZ) * HD;

    // ---- load Q tile (128x128) ----
    for (int i = tid; i < 128 * 32; i += 256) {
        int r = i >> 5, c = (i & 31) << 2;
        float4 v = *(const float4*)(Qb + (size_t)r * HD + c);
        float* q = Qs + r * QS_STRIDE + c;
        q[0] = v.x; q[1] = v.y; q[2] = v.z; q[3] = v.w;
    }

    float m_i[8], l_i[8], O[8][8];
#pragma unroll
    for (int i = 0; i < 8; i++) {
        m_i[i] = -1e30f; l_i[i] = 0.0f;
#pragma unroll
        for (int j = 0; j < 8; j++) O[i][j] = 0.0f;
    }

    const float scale = 0.088388347648318447f;   // 1/sqrt(128)
    const int qi0 = qt * 128 + ty;

    for (int kt = 0; kt <= qt; kt++) {
        __syncthreads();   // prev iter done with Ks(P)/Vs; Qs visible (iter 0)

        // ---- load K, V tiles ----
        const float* Kt = Kb + (size_t)kt * 128 * HD;
        const float* Vt = Vb + (size_t)kt * 128 * HD;
        for (int i = tid; i < 128 * 32; i += 256) {
            int r = i >> 5, c = (i & 31) << 2;
            float4 kv = *(const float4*)(Kt + (size_t)r * HD + c);
            float* ks = Ks + r * QS_STRIDE + c;
            ks[0] = kv.x; ks[1] = kv.y; ks[2] = kv.z; ks[3] = kv.w;
            *(float4*)(Vs + r * 128 + c) = *(const float4*)(Vt + (size_t)r * HD + c);
        }
        __syncthreads();

        // ---- S = Q K^T  (8x8 frag, rows ty+i*16, cols tx+j*16) ----
        float s[8][8];
#pragma unroll
        for (int i = 0; i < 8; i++)
#pragma unroll
            for (int j = 0; j < 8; j++) s[i][j] = 0.0f;

#pragma unroll 4
        for (int kk = 0; kk < 128; kk++) {
            float a[8], bk[8];
#pragma unroll
            for (int i = 0; i < 8; i++) a[i]  = Qs[(ty + i * 16) * QS_STRIDE + kk];
#pragma unroll
            for (int j = 0; j < 8; j++) bk[j] = Ks[(tx + j * 16) * QS_STRIDE + kk];
#pragma unroll
            for (int i = 0; i < 8; i++)
#pragma unroll
                for (int j = 0; j < 8; j++)
                    s[i][j] = fmaf(a[i], bk[j], s[i][j]);
        }

        // ---- mask + online softmax ----
        const int kj0 = kt * 128 + tx;
#pragma unroll
        for (int i = 0; i < 8; i++) {
            int qi = qi0 + i * 16;
            float rm = -1e30f;
#pragma unroll
            for (int j = 0; j < 8; j++) {
                int kj = kj0 + j * 16;
                float v = (kj <= qi) ? s[i][j] * scale : -1e30f;
                s[i][j] = v;
                rm = fmaxf(rm, v);
            }
#pragma unroll
            for (int o = 1; o < 16; o <<= 1)
                rm = fmaxf(rm, __shfl_xor_sync(0xffffffffu, rm, o));
            float mn    = fmaxf(m_i[i], rm);
            float alpha = __expf(m_i[i] - mn);
            m_i[i] = mn;
            float rs = 0.0f;
#pragma unroll
            for (int j = 0; j < 8; j++) {
                float p = __expf(s[i][j] - mn);
                s[i][j] = p;
                rs += p;
            }
#pragma unroll
            for (int o = 1; o < 16; o <<= 1)
                rs += __shfl_xor_sync(0xffffffffu, rs, o);
            l_i[i] = l_i[i] * alpha + rs;
#pragma unroll
            for (int j = 0; j < 8; j++) O[i][j] *= alpha;
        }

        __syncthreads();   // everyone done reading Ks before P overwrites it
#pragma unroll
        for (int i = 0; i < 8; i++)
#pragma unroll
            for (int j = 0; j < 8; j++)
                Ks[(ty + i * 16) * QS_STRIDE + tx + j * 16] = s[i][j];
        __syncthreads();

        // ---- O += P V  (cols tx*8..+7 contiguous for vector V loads) ----
#pragma unroll 4
        for (int kk = 0; kk < 128; kk++) {
            float p[8];
#pragma unroll
            for (int i = 0; i < 8; i++) p[i] = Ks[(ty + i * 16) * QS_STRIDE + kk];
            float4 v0 = *(const float4*)(Vs + kk * 128 + tx * 8);
            float4 v1 = *(const float4*)(Vs + kk * 128 + tx * 8 + 4);
            float vv[8] = {v0.x, v0.y, v0.z, v0.w, v1.x, v1.y, v1.z, v1.w};
#pragma unroll
            for (int i = 0; i < 8; i++)
#pragma unroll
                for (int j = 0; j < 8; j++)
                    O[i][j] = fmaf(p[i], vv[j], O[i][j]);
        }
    }

    // ---- epilogue: O/l -> g_attn[b, t, h*128 + d] ----
#pragma unroll
    for (int i = 0; i < 8; i++) {
        float inv = 1.0f / l_i[i];
        int t = qt * 128 + ty + i * 16;
        float* op = Og + ((size_t)(b * T_SZ + t) * (NH * HD)) + h * HD + tx * 8;
        float4 o0 = make_float4(O[i][0] * inv, O[i][1] * inv, O[i][2] * inv, O[i][3] * inv);
        float4 o1 = make_float4(O[i][4] * inv, O[i][5] * inv, O[i][6] * inv, O[i][7] * inv);
        *(float4*)op       = o0;
        *(float4*)(op + 4) = o1;
    }
}

// ---------------------------------------------------------------------------
// kernel_launch
// ---------------------------------------------------------------------------
extern "C" void kernel_launch(void* const* d_in, const int* in_sizes, int n_in,
                              void* d_out, int out_size)
{
    (void)in_sizes; (void)n_in; (void)out_size;
    const float* hidden = (const float*)d_in[0];
    const float* cosb   = (const float*)d_in[1];
    const float* sinb   = (const float*)d_in[2];
    const float* wq     = (const float*)d_in[3];
    const float* wk     = (const float*)d_in[4];
    const float* wv     = (const float*)d_in[5];
    const float* wo     = (const float*)d_in[6];
    float* out = (float*)d_out;

    float *gq, *gk, *gv, *gattn;
    cudaGetSymbolAddress((void**)&gq,    g_q);
    cudaGetSymbolAddress((void**)&gk,    g_k);
    cudaGetSymbolAddress((void**)&gv,    g_v);
    cudaGetSymbolAddress((void**)&gattn, g_attn);

    const int M = B_SZ * T_SZ;   // 8192

    // QKV projections (NT GEMM), epilogue scatters into [b,h,t,d]
    sgemm_nt<<<dim3(DIM / 128,        M / 128), 256>>>(hidden, wq, gq, M, NH  * HD, DIM, 1, NH);
    sgemm_nt<<<dim3(NKV * HD / 128,   M / 128), 256>>>(hidden, wk, gk, M, NKV * HD, DIM, 1, NKV);
    sgemm_nt<<<dim3(NKV * HD / 128,   M / 128), 256>>>(hidden, wv, gv, M, NKV * HD, DIM, 1, NKV);

    // RoPE on q and k
    rope_kernel<<<B_SZ * NH  * T_SZ, 64>>>(gq, cosb, sinb, NH);
    rope_kernel<<<B_SZ * NKV * T_SZ, 64>>>(gk, cosb, sinb, NKV);

    // Flash attention (causal, GQA)
    size_t smem = (size_t)(2 * 128 * QS_STRIDE + 128 * 128) * sizeof(float);
    cudaFuncSetAttribute(attn_kernel, cudaFuncAttributeMaxDynamicSharedMemorySize, (int)smem);
    attn_kernel<<<dim3(T_SZ / 128, NH, B_SZ), 256, smem>>>(gq, gk, gv, gattn);

    // Output projection
    sgemm_nt<<<dim3(DIM / 128, M / 128), 256>>>(gattn, wo, out, M, DIM, DIM, 0, 0);
}

// round 3
// speedup vs baseline: 1.5886x; 1.5886x over previous
#include <cuda_runtime.h>
#include <cuda_bf16.h>
#include <cstdint>
#include <math.h>

// ---------------------------------------------------------------------------
// Problem constants
// ---------------------------------------------------------------------------
#define B_SZ   4
#define T_SZ   2048
#define DIM    2048
#define NH     16
#define NKV    4
#define HD     128
#define KP     (3 * DIM)          // 6144: bf16x3 split K
#define MTOT   (B_SZ * T_SZ)      // 8192

// ---------------------------------------------------------------------------
// Device scratch (allocation-free rule: __device__ globals)
// ---------------------------------------------------------------------------
__device__ float g_q[(size_t)B_SZ * NH  * T_SZ * HD];   // [b,h,t,d]
__device__ float g_k[(size_t)B_SZ * NKV * T_SZ * HD];
__device__ float g_v[(size_t)B_SZ * NKV * T_SZ * HD];
__device__ float g_attn[(size_t)B_SZ * T_SZ * NH * HD]; // [b,t,h*d]

__device__ __align__(16) __nv_bfloat16 g_ah  [(size_t)MTOT * KP];  // hidden split
__device__ __align__(16) __nv_bfloat16 g_wqkv[(size_t)3072 * KP];  // wq|wk|wv split
__device__ __align__(16) __nv_bfloat16 g_ao  [(size_t)MTOT * KP];  // attn-out split
__device__ __align__(16) __nv_bfloat16 g_woh [(size_t)2048 * KP];  // wo split

// ---------------------------------------------------------------------------
// Helpers (compute_80-level PTX only; NO tcgen05/TMA — not available on
// the harness's compute_103 virtual arch)
// ---------------------------------------------------------------------------
__device__ __forceinline__ uint32_t smem_u32(const void* p) {
    uint32_t a;
    asm("{ .reg .u64 t; cvta.to.shared.u64 t, %1; cvt.u32.u64 %0, t; }" : "=r"(a) : "l"(p));
    return a;
}
#define CP16(dst, src) asm volatile("cp.async.cg.shared.global [%0], [%1], 16;" :: "r"(dst), "l"(src))
#define CP_COMMIT()    asm volatile("cp.async.commit_group;" ::: "memory")
#define CP_WAIT1()     asm volatile("cp.async.wait_group 1;" ::: "memory")

#define LDMX4(r0, r1, r2, r3, addr)                                              \
    asm volatile("ldmatrix.sync.aligned.m8n8.x4.shared.b16 {%0,%1,%2,%3}, [%4];" \
                 : "=r"(r0), "=r"(r1), "=r"(r2), "=r"(r3) : "r"(addr))

#define MMA16816(c, a, b)                                                        \
    asm volatile("mma.sync.aligned.m16n8k16.row.col.f32.bf16.bf16.f32 "          \
                 "{%0,%1,%2,%3}, {%4,%5,%6,%7}, {%8,%9}, {%0,%1,%2,%3};"         \
                 : "+f"((c)[0]), "+f"((c)[1]), "+f"((c)[2]), "+f"((c)[3])        \
                 : "r"((a)[0]), "r"((a)[1]), "r"((a)[2]), "r"((a)[3]),           \
                   "r"((b)[0]), "r"((b)[1]))

// ---------------------------------------------------------------------------
// fp32 -> bf16x3 split conversion.
// mode 0 (A-side): out[k]=hi, out[DIM+k]=hi, out[2*DIM+k]=lo
// mode 1 (B-side): out[k]=hi, out[DIM+k]=lo, out[2*DIM+k]=hi
// ---------------------------------------------------------------------------
__global__ void convert_split(const float* __restrict__ src,
                              __nv_bfloat16* __restrict__ dst, int mode)
{
    size_t i = ((size_t)blockIdx.x * blockDim.x + threadIdx.x) * 4;
    size_t row = i / DIM;
    int k = (int)(i % DIM);
    float4 x = *(const float4*)(src + i);
    float xs[4] = {x.x, x.y, x.z, x.w};
    __nv_bfloat16 h[4], l[4];
#pragma unroll
    for (int j = 0; j < 4; j++) {
        h[j] = __float2bfloat16_rn(xs[j]);
        l[j] = __float2bfloat16_rn(xs[j] - __bfloat162float(h[j]));
    }
    __nv_bfloat16* base = dst + row * KP + k;
    *(__nv_bfloat162*)(base)     = __nv_bfloat162(h[0], h[1]);
    *(__nv_bfloat162*)(base + 2) = __nv_bfloat162(h[2], h[3]);
    __nv_bfloat16* m1 = base + DIM;
    __nv_bfloat16* m2 = base + 2 * DIM;
    if (mode == 1) { __nv_bfloat16* t = m1; m1 = m2; m2 = t; }
    *(__nv_bfloat162*)(m1)     = __nv_bfloat162(h[0], h[1]);
    *(__nv_bfloat162*)(m1 + 2) = __nv_bfloat162(h[2], h[3]);
    *(__nv_bfloat162*)(m2)     = __nv_bfloat162(l[0], l[1]);
    *(__nv_bfloat162*)(m2 + 2) = __nv_bfloat162(l[2], l[3]);
}

// ---------------------------------------------------------------------------
// mma.sync bf16 NT GEMM:  C[m,n] = sum_k A[m,k] * B[n,k], K' = 6144.
// Tile 128x128x64, 3-stage cp.async pipeline, 8 warps (2M x 4N), warp 64x32.
// smem rows padded to 72 halves (144 B) -> conflict-free ldmatrix.
// mode 0: C row-major [M, ldc] into Cq
// mode 1: QKV scatter: n<2048 -> q[b,h,t,d]; <2560 -> k; else v
// ---------------------------------------------------------------------------
#define BM 128
#define BN 128
#define BK 64
#define NS 3
#define KITERS (KP / BK)                 // 96
#define ROWB   144                       // bytes per smem row (72 halves)
#define MAT_BYTES (128 * ROWB)           // 18432
#define STAGE_BYTES (2 * MAT_BYTES)      // 36864
#define GEMM_SMEM (NS * STAGE_BYTES)     // 110592

__device__ __forceinline__ void load_stage(uint32_t st, const char* Arow,
                                           const char* Brow, int it, int tid)
{
    const size_t lda = (size_t)KP * 2;
    const char* As = Arow + (size_t)it * (BK * 2);
    const char* Bs = Brow + (size_t)it * (BK * 2);
#pragma unroll
    for (int x = 0; x < 4; x++) {                  // A: 1024 16B chunks
        int idx = tid + x * 256;
        int r = idx >> 3, c = (idx & 7) << 4;
        CP16(st + r * ROWB + c, As + (size_t)r * lda + c);
    }
    uint32_t bb = st + MAT_BYTES;
#pragma unroll
    for (int x = 0; x < 4; x++) {                  // B: 1024 16B chunks
        int idx = tid + x * 256;
        int r = idx >> 3, c = (idx & 7) << 4;
        CP16(bb + r * ROWB + c, Bs + (size_t)r * lda + c);
    }
}

__global__ __launch_bounds__(256, 1) void gemm_mma_bf16x3(
    const __nv_bfloat16* __restrict__ Ag, const __nv_bfloat16* __restrict__ Bg,
    float* __restrict__ Cq, float* __restrict__ Ck, float* __restrict__ Cv,
    int mode, int ldc)
{
    extern __shared__ char smraw[];
    const uint32_t sm0 = smem_u32(smraw);

    const int tid  = threadIdx.x;
    const int wid  = tid >> 5;
    const int lane = tid & 31;
    const int wm   = wid >> 2;     // 0..1  (64 rows each)
    const int wn   = wid & 3;      // 0..3  (32 cols each)
    const int bn   = blockIdx.x * BN;
    const int bm   = blockIdx.y * BM;

    const char* Arow = (const char*)Ag + (size_t)bm * KP * 2;
    const char* Brow = (const char*)Bg + (size_t)bn * KP * 2;

    float c[4][4][4];
#pragma unroll
    for (int i = 0; i < 4; i++)
#pragma unroll
        for (int j = 0; j < 4; j++)
#pragma unroll
            for (int e = 0; e < 4; e++) c[i][j][e] = 0.0f;

    load_stage(sm0,               Arow, Brow, 0, tid); CP_COMMIT();
    load_stage(sm0 + STAGE_BYTES, Arow, Brow, 1, tid); CP_COMMIT();

    // per-warp ldmatrix lane addressing (byte offsets within the tile)
    const int a_row = wm * 64 + (lane & 15);          // + mf*16
    const int a_col = (lane >> 4) << 3;               // + kk*16 (halves)
    const int b_row = wn * 32 + ((lane >> 4) << 3) + (lane & 7);  // + p*16
    const int b_col = ((lane >> 3) & 1) << 3;         // + kk*16 (halves)

    int slot = 0;
    for (int it = 0; it < KITERS; it++) {
        CP_WAIT1();
        __syncthreads();

        if (it + 2 < KITERS) {
            int ns = slot + 2; if (ns >= NS) ns -= NS;
            load_stage(sm0 + ns * STAGE_BYTES, Arow, Brow, it + 2, tid);
        }
        CP_COMMIT();

        const uint32_t sa = sm0 + slot * STAGE_BYTES;
        const uint32_t sb = sa + MAT_BYTES;

#pragma unroll
        for (int kk = 0; kk < 4; kk++) {
            uint32_t af[4][4], bf[4][2];
#pragma unroll
            for (int mf = 0; mf < 4; mf++) {
                uint32_t addr = sa + (a_row + mf * 16) * ROWB + (a_col + kk * 16) * 2;
                LDMX4(af[mf][0], af[mf][1], af[mf][2], af[mf][3], addr);
            }
#pragma unroll
            for (int p = 0; p < 2; p++) {
                uint32_t r0, r1, r2, r3;
                uint32_t addr = sb + (b_row + p * 16) * ROWB + (b_col + kk * 16) * 2;
                LDMX4(r0, r1, r2, r3, addr);
                bf[2 * p][0] = r0;     bf[2 * p][1] = r1;
                bf[2 * p + 1][0] = r2; bf[2 * p + 1][1] = r3;
            }
#pragma unroll
            for (int mf = 0; mf < 4; mf++)
#pragma unroll
                for (int nf = 0; nf < 4; nf++)
                    MMA16816(c[mf][nf], af[mf], bf[nf]);
        }
        slot++; if (slot == NS) slot = 0;
    }

    // ---- epilogue ----
    const int mrow = bm + wm * 64 + (lane >> 2);
    const int ncol = bn + wn * 32 + (lane & 3) * 2;
#pragma unroll
    for (int mf = 0; mf < 4; mf++) {
#pragma unroll
        for (int half = 0; half < 2; half++) {
            const int m = mrow + mf * 16 + half * 8;
            float* pbase;
            if (mode == 0) {
                pbase = Cq + (size_t)m * ldc;
            } else {
                int b = m >> 11, t = m & (T_SZ - 1);
                // head resolved per n below; precompute b,t here
                pbase = nullptr;
#pragma unroll
                for (int nf = 0; nf < 4; nf++) {
                    int n = ncol + nf * 8;
                    float* p;
                    if (n < 2048) {
                        int hh = n >> 7, d = n & 127;
                        p = Cq + ((((size_t)b * NH + hh) * T_SZ + t) * HD + d);
                    } else if (n < 2560) {
                        int x = n - 2048; int hh = x >> 7, d = x & 127;
                        p = Ck + ((((size_t)b * NKV + hh) * T_SZ + t) * HD + d);
                    } else {
                        int x = n - 2560; int hh = x >> 7, d = x & 127;
                        p = Cv + ((((size_t)b * NKV + hh) * T_SZ + t) * HD + d);
                    }
                    float2 v = make_float2(c[mf][nf][half * 2], c[mf][nf][half * 2 + 1]);
                    *(float2*)p = v;
                }
                continue;
            }
#pragma unroll
            for (int nf = 0; nf < 4; nf++) {
                float2 v = make_float2(c[mf][nf][half * 2], c[mf][nf][half * 2 + 1]);
                *(float2*)(pbase + ncol + nf * 8) = v;
            }
        }
    }
}

// ---------------------------------------------------------------------------
// RoPE in-place on [b, h, t, 128] tensors.
// ---------------------------------------------------------------------------
__global__ void rope_kernel(float* __restrict__ x,
                            const float* __restrict__ cosb,
                            const float* __restrict__ sinb, int nh)
{
    const int d   = threadIdx.x & 63;
    const int idx = blockIdx.x * 4 + (threadIdx.x >> 6);
    const int t   = idx & (T_SZ - 1);
    const int bh  = idx >> 11;
    const int b   = bh / nh;

    float* p = x + (size_t)idx * HD;
    const float* cp = cosb + ((size_t)b * T_SZ + t) * HD;
    const float* sp = sinb + ((size_t)b * T_SZ + t) * HD;

    float x1 = p[d], x2 = p[d + 64];
    p[d]      = x1 * cp[d]      - x2 * sp[d];
    p[d + 64] = x2 * cp[d + 64] + x1 * sp[d + 64];
}

// ---------------------------------------------------------------------------
// Flash attention, fp32, causal (unchanged — proven correct at R1).
// ---------------------------------------------------------------------------
#define QS_STRIDE 129
__global__ __launch_bounds__(256, 1) void attn_kernel(
    const float* __restrict__ Qg, const float* __restrict__ Kg,
    const float* __restrict__ Vg, float* __restrict__ Og)
{
    extern __shared__ float sm[];
    float* Qs = sm;
    float* Ks = sm + 128 * QS_STRIDE;
    float* Vs = sm + 2 * 128 * QS_STRIDE;

    const int tid = threadIdx.x;
    const int tx  = tid & 15;
    const int ty  = tid >> 4;
    const int qt  = blockIdx.x;
    const int h   = blockIdx.y;
    const int b   = blockIdx.z;
    const int hk  = h >> 2;

    const float* Qb = Qg + (((size_t)(b * NH  + h ) * T_SZ) + qt * 128) * HD;
    const float* Kb = Kg + ((size_t)(b * NKV + hk) * T_SZ) * HD;
    const float* Vb = Vg + ((size_t)(b * NKV + hk) * T_SZ) * HD;

    for (int i = tid; i < 128 * 32; i += 256) {
        int r = i >> 5, c = (i & 31) << 2;
        float4 v = *(const float4*)(Qb + (size_t)r * HD + c);
        float* q = Qs + r * QS_STRIDE + c;
        q[0] = v.x; q[1] = v.y; q[2] = v.z; q[3] = v.w;
    }

    float m_i[8], l_i[8], O[8][8];
#pragma unroll
    for (int i = 0; i < 8; i++) {
        m_i[i] = -1e30f; l_i[i] = 0.0f;
#pragma unroll
        for (int j = 0; j < 8; j++) O[i][j] = 0.0f;
    }

    const float scale = 0.088388347648318447f;
    const int qi0 = qt * 128 + ty;

    for (int kt = 0; kt <= qt; kt++) {
        __syncthreads();
        const float* Kt = Kb + (size_t)kt * 128 * HD;
        const float* Vt = Vb + (size_t)kt * 128 * HD;
        for (int i = tid; i < 128 * 32; i += 256) {
            int r = i >> 5, c = (i & 31) << 2;
            float4 kv = *(const float4*)(Kt + (size_t)r * HD + c);
            float* ks = Ks + r * QS_STRIDE + c;
            ks[0] = kv.x; ks[1] = kv.y; ks[2] = kv.z; ks[3] = kv.w;
            *(float4*)(Vs + r * 128 + c) = *(const float4*)(Vt + (size_t)r * HD + c);
        }
        __syncthreads();

        float s[8][8];
#pragma unroll
        for (int i = 0; i < 8; i++)
#pragma unroll
            for (int j = 0; j < 8; j++) s[i][j] = 0.0f;

#pragma unroll 4
        for (int kk = 0; kk < 128; kk++) {
            float a[8], bk[8];
#pragma unroll
            for (int i = 0; i < 8; i++) a[i]  = Qs[(ty + i * 16) * QS_STRIDE + kk];
#pragma unroll
            for (int j = 0; j < 8; j++) bk[j] = Ks[(tx + j * 16) * QS_STRIDE + kk];
#pragma unroll
            for (int i = 0; i < 8; i++)
#pragma unroll
                for (int j = 0; j < 8; j++)
                    s[i][j] = fmaf(a[i], bk[j], s[i][j]);
        }

        const int kj0 = kt * 128 + tx;
#pragma unroll
        for (int i = 0; i < 8; i++) {
            int qi = qi0 + i * 16;
            float rm = -1e30f;
#pragma unroll
            for (int j = 0; j < 8; j++) {
                int kj = kj0 + j * 16;
                float v = (kj <= qi) ? s[i][j] * scale : -1e30f;
                s[i][j] = v;
                rm = fmaxf(rm, v);
            }
#pragma unroll
            for (int o = 1; o < 16; o <<= 1)
                rm = fmaxf(rm, __shfl_xor_sync(0xffffffffu, rm, o));
            float mn    = fmaxf(m_i[i], rm);
            float alpha = __expf(m_i[i] - mn);
            m_i[i] = mn;
            float rs = 0.0f;
#pragma unroll
            for (int j = 0; j < 8; j++) {
                float p = __expf(s[i][j] - mn);
                s[i][j] = p;
                rs += p;
            }
#pragma unroll
            for (int o = 1; o < 16; o <<= 1)
                rs += __shfl_xor_sync(0xffffffffu, rs, o);
            l_i[i] = l_i[i] * alpha + rs;
#pragma unroll
            for (int j = 0; j < 8; j++) O[i][j] *= alpha;
        }

        __syncthreads();
#pragma unroll
        for (int i = 0; i < 8; i++)
#pragma unroll
            for (int j = 0; j < 8; j++)
                Ks[(ty + i * 16) * QS_STRIDE + tx + j * 16] = s[i][j];
        __syncthreads();

#pragma unroll 4
        for (int kk = 0; kk < 128; kk++) {
            float p[8];
#pragma unroll
            for (int i = 0; i < 8; i++) p[i] = Ks[(ty + i * 16) * QS_STRIDE + kk];
            float4 v0 = *(const float4*)(Vs + kk * 128 + tx * 8);
            float4 v1 = *(const float4*)(Vs + kk * 128 + tx * 8 + 4);
            float vv[8] = {v0.x, v0.y, v0.z, v0.w, v1.x, v1.y, v1.z, v1.w};
#pragma unroll
            for (int i = 0; i < 8; i++)
#pragma unroll
                for (int j = 0; j < 8; j++)
                    O[i][j] = fmaf(p[i], vv[j], O[i][j]);
        }
    }

#pragma unroll
    for (int i = 0; i < 8; i++) {
        float inv = 1.0f / l_i[i];
        int t = qt * 128 + ty + i * 16;
        float* op = Og + ((size_t)(b * T_SZ + t) * (NH * HD)) + h * HD + tx * 8;
        float4 o0 = make_float4(O[i][0] * inv, O[i][1] * inv, O[i][2] * inv, O[i][3] * inv);
        float4 o1 = make_float4(O[i][4] * inv, O[i][5] * inv, O[i][6] * inv, O[i][7] * inv);
        *(float4*)op       = o0;
        *(float4*)(op + 4) = o1;
    }
}

// ---------------------------------------------------------------------------
// kernel_launch
// ---------------------------------------------------------------------------
extern "C" void kernel_launch(void* const* d_in, const int* in_sizes, int n_in,
                              void* d_out, int out_size)
{
    (void)in_sizes; (void)n_in; (void)out_size;
    const float* hidden = (const float*)d_in[0];
    const float* cosb   = (const float*)d_in[1];
    const float* sinb   = (const float*)d_in[2];
    const float* wq     = (const float*)d_in[3];
    const float* wk     = (const float*)d_in[4];
    const float* wv     = (const float*)d_in[5];
    const float* wo     = (const float*)d_in[6];
    float* out = (float*)d_out;

    float *gq, *gk, *gv, *gattn;
    __nv_bfloat16 *gah, *gwqkv, *gao, *gwoh;
    cudaGetSymbolAddress((void**)&gq,    g_q);
    cudaGetSymbolAddress((void**)&gk,    g_k);
    cudaGetSymbolAddress((void**)&gv,    g_v);
    cudaGetSymbolAddress((void**)&gattn, g_attn);
    cudaGetSymbolAddress((void**)&gah,   g_ah);
    cudaGetSymbolAddress((void**)&gwqkv, g_wqkv);
    cudaGetSymbolAddress((void**)&gao,   g_ao);
    cudaGetSymbolAddress((void**)&gwoh,  g_woh);

    size_t asmem = (size_t)(2 * 128 * QS_STRIDE + 128 * 128) * sizeof(float);
    cudaFuncSetAttribute(attn_kernel, cudaFuncAttributeMaxDynamicSharedMemorySize, (int)asmem);
    cudaFuncSetAttribute(gemm_mma_bf16x3, cudaFuncAttributeMaxDynamicSharedMemorySize, GEMM_SMEM);

    // --- bf16x3 conversions ---
    convert_split<<<MTOT * DIM / 4 / 256, 256>>>(hidden, gah, 0);
    convert_split<<<2048 * DIM / 4 / 256, 256>>>(wq, gwqkv, 1);
    convert_split<<< 512 * DIM / 4 / 256, 256>>>(wk, gwqkv + (size_t)2048 * KP, 1);
    convert_split<<< 512 * DIM / 4 / 256, 256>>>(wv, gwqkv + (size_t)2560 * KP, 1);
    convert_split<<<2048 * DIM / 4 / 256, 256>>>(wo, gwoh, 1);

    // --- fused QKV projection (mma.sync bf16x3), scatter epilogue ---
    gemm_mma_bf16x3<<<dim3(3072 / BN, MTOT / BM), 256, GEMM_SMEM>>>(
        gah, gwqkv, gq, gk, gv, 1, 0);

    // --- RoPE ---
    rope_kernel<<<B_SZ * NH  * T_SZ / 4, 256>>>(gq, cosb, sinb, NH);
    rope_kernel<<<B_SZ * NKV * T_SZ / 4, 256>>>(gk, cosb, sinb, NKV);

    // --- Flash attention (fp32, causal, GQA) ---
    attn_kernel<<<dim3(T_SZ / 128, NH, B_SZ), 256, asmem>>>(gq, gk, gv, gattn);

    // --- convert attention output, then wo projection ---
    convert_split<<<MTOT * DIM / 4 / 256, 256>>>(gattn, gao, 0);
    gemm_mma_bf16x3<<<dim3(DIM / BN, MTOT / BM), 256, GEMM_SMEM>>>(
        gao, gwoh, out, nullptr, nullptr, 0, DIM);
}

// round 4
// speedup vs baseline: 1.8522x; 1.1659x over previous
#include <cuda_runtime.h>
#include <cuda_bf16.h>
#include <cstdint>
#include <math.h>

// ---------------------------------------------------------------------------
// Problem constants
// ---------------------------------------------------------------------------
#define B_SZ   4
#define T_SZ   2048
#define DIM    2048
#define NH     16
#define NKV    4
#define HD     128
#define KP     (3 * DIM)          // 6144: bf16x3 split K
#define MTOT   (B_SZ * T_SZ)      // 8192

// ---------------------------------------------------------------------------
// Device scratch
// ---------------------------------------------------------------------------
__device__ float g_q[(size_t)B_SZ * NH  * T_SZ * HD];   // [b,h,t,d] fp32
__device__ float g_k[(size_t)B_SZ * NKV * T_SZ * HD];
__device__ float g_v[(size_t)B_SZ * NKV * T_SZ * HD];

__device__ __align__(16) __nv_bfloat16 g_qh[(size_t)B_SZ * NH  * T_SZ * HD];
__device__ __align__(16) __nv_bfloat16 g_ql[(size_t)B_SZ * NH  * T_SZ * HD];
__device__ __align__(16) __nv_bfloat16 g_kh[(size_t)B_SZ * NKV * T_SZ * HD];
__device__ __align__(16) __nv_bfloat16 g_kl[(size_t)B_SZ * NKV * T_SZ * HD];
__device__ __align__(16) __nv_bfloat16 g_vh[(size_t)B_SZ * NKV * T_SZ * HD];
__device__ __align__(16) __nv_bfloat16 g_vl[(size_t)B_SZ * NKV * T_SZ * HD];

__device__ __align__(16) __nv_bfloat16 g_ah  [(size_t)MTOT * KP];  // hidden split
__device__ __align__(16) __nv_bfloat16 g_wqkv[(size_t)3072 * KP];  // wq|wk|wv split
__device__ __align__(16) __nv_bfloat16 g_ao  [(size_t)MTOT * KP];  // attn-out split
__device__ __align__(16) __nv_bfloat16 g_woh [(size_t)2048 * KP];  // wo split

// ---------------------------------------------------------------------------
// Helpers (compute_80-level PTX only — harness compiles via compute_103,
// which feature-gates tcgen05/TMA; mma.sync/ldmatrix/cp.async are fine)
// ---------------------------------------------------------------------------
__device__ __forceinline__ uint32_t smem_u32(const void* p) {
    uint32_t a;
    asm("{ .reg .u64 t; cvta.to.shared.u64 t, %1; cvt.u32.u64 %0, t; }" : "=r"(a) : "l"(p));
    return a;
}
#define CP16(dst, src) asm volatile("cp.async.cg.shared.global [%0], [%1], 16;" :: "r"(dst), "l"(src))
#define CP_COMMIT()    asm volatile("cp.async.commit_group;" ::: "memory")
#define CP_WAIT1()     asm volatile("cp.async.wait_group 1;" ::: "memory")
#define CP_WAIT0()     asm volatile("cp.async.wait_group 0;" ::: "memory")

#define LDMX4(r0, r1, r2, r3, addr)                                              \
    asm volatile("ldmatrix.sync.aligned.m8n8.x4.shared.b16 {%0,%1,%2,%3}, [%4];" \
                 : "=r"(r0), "=r"(r1), "=r"(r2), "=r"(r3) : "r"(addr))

#define LDMX4T(r0, r1, r2, r3, addr)                                                   \
    asm volatile("ldmatrix.sync.aligned.m8n8.x4.trans.shared.b16 {%0,%1,%2,%3}, [%4];" \
                 : "=r"(r0), "=r"(r1), "=r"(r2), "=r"(r3) : "r"(addr))

#define MMA16816(c, a, b)                                                        \
    asm volatile("mma.sync.aligned.m16n8k16.row.col.f32.bf16.bf16.f32 "          \
                 "{%0,%1,%2,%3}, {%4,%5,%6,%7}, {%8,%9}, {%0,%1,%2,%3};"         \
                 : "+f"((c)[0]), "+f"((c)[1]), "+f"((c)[2]), "+f"((c)[3])        \
                 : "r"((a)[0]), "r"((a)[1]), "r"((a)[2]), "r"((a)[3]),           \
                   "r"((b)[0]), "r"((b)[1]))

__device__ __forceinline__ uint32_t pack_bf16x2(float lo, float hi) {
    __nv_bfloat162 v = __floats2bfloat162_rn(lo, hi);
    return *(uint32_t*)&v;
}

// ---------------------------------------------------------------------------
// fp32 -> bf16x3 split conversion (A-side / B-side layouts for GEMM)
// ---------------------------------------------------------------------------
__global__ void convert_split(const float* __restrict__ src,
                              __nv_bfloat16* __restrict__ dst, int mode)
{
    size_t i = ((size_t)blockIdx.x * blockDim.x + threadIdx.x) * 4;
    size_t row = i / DIM;
    int k = (int)(i % DIM);
    float4 x = *(const float4*)(src + i);
    float xs[4] = {x.x, x.y, x.z, x.w};
    __nv_bfloat16 h[4], l[4];
#pragma unroll
    for (int j = 0; j < 4; j++) {
        h[j] = __float2bfloat16_rn(xs[j]);
        l[j] = __float2bfloat16_rn(xs[j] - __bfloat162float(h[j]));
    }
    __nv_bfloat16* base = dst + row * KP + k;
    *(__nv_bfloat162*)(base)     = __nv_bfloat162(h[0], h[1]);
    *(__nv_bfloat162*)(base + 2) = __nv_bfloat162(h[2], h[3]);
    __nv_bfloat16* m1 = base + DIM;
    __nv_bfloat16* m2 = base + 2 * DIM;
    if (mode == 1) { __nv_bfloat16* t = m1; m1 = m2; m2 = t; }
    *(__nv_bfloat162*)(m1)     = __nv_bfloat162(h[0], h[1]);
    *(__nv_bfloat162*)(m1 + 2) = __nv_bfloat162(h[2], h[3]);
    *(__nv_bfloat162*)(m2)     = __nv_bfloat162(l[0], l[1]);
    *(__nv_bfloat162*)(m2 + 2) = __nv_bfloat162(l[2], l[3]);
}

// ---------------------------------------------------------------------------
// mma.sync bf16 NT GEMM (unchanged from R3 — proven)
// ---------------------------------------------------------------------------
#define BM 128
#define BN 128
#define BK 64
#define NS 3
#define KITERS (KP / BK)                 // 96
#define ROWB   144
#define MAT_BYTES (128 * ROWB)
#define STAGE_BYTES (2 * MAT_BYTES)
#define GEMM_SMEM (NS * STAGE_BYTES)

__device__ __forceinline__ void load_stage(uint32_t st, const char* Arow,
                                           const char* Brow, int it, int tid)
{
    const size_t lda = (size_t)KP * 2;
    const char* As = Arow + (size_t)it * (BK * 2);
    const char* Bs = Brow + (size_t)it * (BK * 2);
#pragma unroll
    for (int x = 0; x < 4; x++) {
        int idx = tid + x * 256;
        int r = idx >> 3, c = (idx & 7) << 4;
        CP16(st + r * ROWB + c, As + (size_t)r * lda + c);
    }
    uint32_t bb = st + MAT_BYTES;
#pragma unroll
    for (int x = 0; x < 4; x++) {
        int idx = tid + x * 256;
        int r = idx >> 3, c = (idx & 7) << 4;
        CP16(bb + r * ROWB + c, Bs + (size_t)r * lda + c);
    }
}

__global__ __launch_bounds__(256, 1) void gemm_mma_bf16x3(
    const __nv_bfloat16* __restrict__ Ag, const __nv_bfloat16* __restrict__ Bg,
    float* __restrict__ Cq, float* __restrict__ Ck, float* __restrict__ Cv,
    int mode, int ldc)
{
    extern __shared__ char smraw[];
    const uint32_t sm0 = smem_u32(smraw);

    const int tid  = threadIdx.x;
    const int wid  = tid >> 5;
    const int lane = tid & 31;
    const int wm   = wid >> 2;
    const int wn   = wid & 3;
    const int bn   = blockIdx.x * BN;
    const int bm   = blockIdx.y * BM;

    const char* Arow = (const char*)Ag + (size_t)bm * KP * 2;
    const char* Brow = (const char*)Bg + (size_t)bn * KP * 2;

    float c[4][4][4];
#pragma unroll
    for (int i = 0; i < 4; i++)
#pragma unroll
        for (int j = 0; j < 4; j++)
#pragma unroll
            for (int e = 0; e < 4; e++) c[i][j][e] = 0.0f;

    load_stage(sm0,               Arow, Brow, 0, tid); CP_COMMIT();
    load_stage(sm0 + STAGE_BYTES, Arow, Brow, 1, tid); CP_COMMIT();

    const int a_row = wm * 64 + (lane & 15);
    const int a_col = (lane >> 4) << 3;
    const int b_row = wn * 32 + ((lane >> 4) << 3) + (lane & 7);
    const int b_col = ((lane >> 3) & 1) << 3;

    int slot = 0;
    for (int it = 0; it < KITERS; it++) {
        CP_WAIT1();
        __syncthreads();

        if (it + 2 < KITERS) {
            int ns = slot + 2; if (ns >= NS) ns -= NS;
            load_stage(sm0 + ns * STAGE_BYTES, Arow, Brow, it + 2, tid);
        }
        CP_COMMIT();

        const uint32_t sa = sm0 + slot * STAGE_BYTES;
        const uint32_t sb = sa + MAT_BYTES;

#pragma unroll
        for (int kk = 0; kk < 4; kk++) {
            uint32_t af[4][4], bf[4][2];
#pragma unroll
            for (int mf = 0; mf < 4; mf++) {
                uint32_t addr = sa + (a_row + mf * 16) * ROWB + (a_col + kk * 16) * 2;
                LDMX4(af[mf][0], af[mf][1], af[mf][2], af[mf][3], addr);
            }
#pragma unroll
            for (int p = 0; p < 2; p++) {
                uint32_t r0, r1, r2, r3;
                uint32_t addr = sb + (b_row + p * 16) * ROWB + (b_col + kk * 16) * 2;
                LDMX4(r0, r1, r2, r3, addr);
                bf[2 * p][0] = r0;     bf[2 * p][1] = r1;
                bf[2 * p + 1][0] = r2; bf[2 * p + 1][1] = r3;
            }
#pragma unroll
            for (int mf = 0; mf < 4; mf++)
#pragma unroll
                for (int nf = 0; nf < 4; nf++)
                    MMA16816(c[mf][nf], af[mf], bf[nf]);
        }
        slot++; if (slot == NS) slot = 0;
    }

    const int mrow = bm + wm * 64 + (lane >> 2);
    const int ncol = bn + wn * 32 + (lane & 3) * 2;
#pragma unroll
    for (int mf = 0; mf < 4; mf++) {
#pragma unroll
        for (int half = 0; half < 2; half++) {
            const int m = mrow + mf * 16 + half * 8;
            if (mode == 0) {
                float* pbase = Cq + (size_t)m * ldc;
#pragma unroll
                for (int nf = 0; nf < 4; nf++) {
                    float2 v = make_float2(c[mf][nf][half * 2], c[mf][nf][half * 2 + 1]);
                    *(float2*)(pbase + ncol + nf * 8) = v;
                }
            } else {
                int b = m >> 11, t = m & (T_SZ - 1);
#pragma unroll
                for (int nf = 0; nf < 4; nf++) {
                    int n = ncol + nf * 8;
                    float* p;
                    if (n < 2048) {
                        int hh = n >> 7, d = n & 127;
                        p = Cq + ((((size_t)b * NH + hh) * T_SZ + t) * HD + d);
                    } else if (n < 2560) {
                        int x = n - 2048; int hh = x >> 7, d = x & 127;
                        p = Ck + ((((size_t)b * NKV + hh) * T_SZ + t) * HD + d);
                    } else {
                        int x = n - 2560; int hh = x >> 7, d = x & 127;
                        p = Cv + ((((size_t)b * NKV + hh) * T_SZ + t) * HD + d);
                    }
                    float2 v = make_float2(c[mf][nf][half * 2], c[mf][nf][half * 2 + 1]);
                    *(float2*)p = v;
                }
            }
        }
    }
}

// ---------------------------------------------------------------------------
// RoPE + hi/lo bf16 split: fp32 [b,nh,t,128] -> (hi, lo) bf16 planes.
// scale folded in (for Q). 256 threads = 4 rows/block.
// ---------------------------------------------------------------------------
__global__ void rope_split(const float* __restrict__ x,
                           const float* __restrict__ cosb,
                           const float* __restrict__ sinb,
                           __nv_bfloat16* __restrict__ oh,
                           __nv_bfloat16* __restrict__ ol,
                           int nh, float scale)
{
    const int d   = threadIdx.x & 63;
    const int idx = blockIdx.x * 4 + (threadIdx.x >> 6);
    const int t   = idx & (T_SZ - 1);
    const int bh  = idx >> 11;
    const int b   = bh / nh;

    const float* p  = x + (size_t)idx * HD;
    const float* cp = cosb + ((size_t)b * T_SZ + t) * HD;
    const float* sp = sinb + ((size_t)b * T_SZ + t) * HD;

    float x1 = p[d], x2 = p[d + 64];
    float o1 = (x1 * cp[d]      - x2 * sp[d])      * scale;
    float o2 = (x2 * cp[d + 64] + x1 * sp[d + 64]) * scale;

    __nv_bfloat16 h1 = __float2bfloat16_rn(o1);
    __nv_bfloat16 h2 = __float2bfloat16_rn(o2);
    oh[(size_t)idx * HD + d]      = h1;
    oh[(size_t)idx * HD + d + 64] = h2;
    ol[(size_t)idx * HD + d]      = __float2bfloat16_rn(o1 - __bfloat162float(h1));
    ol[(size_t)idx * HD + d + 64] = __float2bfloat16_rn(o2 - __bfloat162float(h2));
}

// elementwise hi/lo split (V)
__global__ void split_hl(const float* __restrict__ x,
                         __nv_bfloat16* __restrict__ oh,
                         __nv_bfloat16* __restrict__ ol)
{
    size_t i = ((size_t)blockIdx.x * blockDim.x + threadIdx.x) * 4;
    float4 v = *(const float4*)(x + i);
    float xs[4] = {v.x, v.y, v.z, v.w};
    __nv_bfloat16 h[4], l[4];
#pragma unroll
    for (int j = 0; j < 4; j++) {
        h[j] = __float2bfloat16_rn(xs[j]);
        l[j] = __float2bfloat16_rn(xs[j] - __bfloat162float(h[j]));
    }
    *(__nv_bfloat162*)(oh + i)     = __nv_bfloat162(h[0], h[1]);
    *(__nv_bfloat162*)(oh + i + 2) = __nv_bfloat162(h[2], h[3]);
    *(__nv_bfloat162*)(ol + i)     = __nv_bfloat162(l[0], l[1]);
    *(__nv_bfloat162*)(ol + i + 2) = __nv_bfloat162(l[2], l[3]);
}

// ---------------------------------------------------------------------------
// Flash attention with mma.sync bf16 split-precision.
// Block: 128 q-rows x (head, batch). 8 warps x 16 rows. KV tiles of 128.
// smem planes (pitch 264 halves = 528 B, conflict-free ldmatrix):
//   Qs[128][hi:0-127 | lo:128-255], Ks same, Vs same.
// S = Qh*Kh + Qh*Kl + Ql*Kh (scale pre-folded into Q)
// O = Ph*Vh + Ph*Vl + Pl*Vh  (P split in registers; C-frag == A-frag layout)
// Epilogue writes bf16x3 A-layout rows of g_ao directly.
// ---------------------------------------------------------------------------
#define AP    264                         // pitch in halves
#define APB   (AP * 2)                    // 528 bytes
#define PLANE (128 * APB)                 // 67584 bytes
#define ATT_SMEM (3 * PLANE)              // 202752 bytes

__global__ __launch_bounds__(256, 1) void attn_mma(
    const __nv_bfloat16* __restrict__ Qh, const __nv_bfloat16* __restrict__ Ql,
    const __nv_bfloat16* __restrict__ Kh, const __nv_bfloat16* __restrict__ Kl,
    const __nv_bfloat16* __restrict__ Vh, const __nv_bfloat16* __restrict__ Vl,
    __nv_bfloat16* __restrict__ Ao)
{
    extern __shared__ char smraw[];
    const uint32_t Qs = smem_u32(smraw);
    const uint32_t Ks = Qs + PLANE;
    const uint32_t Vs = Qs + 2 * PLANE;

    const int tid  = threadIdx.x;
    const int wid  = tid >> 5;
    const int lane = tid & 31;
    const int qt   = 15 - blockIdx.x;       // heavy blocks first
    const int h    = blockIdx.y;
    const int b    = blockIdx.z;
    const int hk   = h >> 2;

    const char* Qhb = (const char*)(Qh + (((size_t)(b * NH + h) * T_SZ) + qt * 128) * HD);
    const char* Qlb = (const char*)(Ql + (((size_t)(b * NH + h) * T_SZ) + qt * 128) * HD);
    const char* Khb = (const char*)(Kh + ((size_t)(b * NKV + hk) * T_SZ) * HD);
    const char* Klb = (const char*)(Kl + ((size_t)(b * NKV + hk) * T_SZ) * HD);
    const char* Vhb = (const char*)(Vh + ((size_t)(b * NKV + hk) * T_SZ) * HD);
    const char* Vlb = (const char*)(Vl + ((size_t)(b * NKV + hk) * T_SZ) * HD);

    // ---- load Q tile (hi + lo) ----
#pragma unroll
    for (int x = 0; x < 16; x++) {
        int idx = tid + x * 256;            // 4096 chunks
        int r = idx >> 5, sub = idx & 31;
        int pl = sub >> 4, cc = sub & 15;
        const char* src = (pl ? Qlb : Qhb) + (size_t)r * 256 + cc * 16;
        CP16(Qs + r * APB + pl * 256 + cc * 16, src);
    }
    CP_COMMIT();

    float m_i[2], l_i[2], O[16][4];
#pragma unroll
    for (int rh = 0; rh < 2; rh++) { m_i[rh] = -1e30f; l_i[rh] = 0.0f; }
#pragma unroll
    for (int nf = 0; nf < 16; nf++)
#pragma unroll
        for (int e = 0; e < 4; e++) O[nf][e] = 0.0f;

    const int arow = (wid * 16 + (lane & 15)) * APB + (((lane >> 4) << 3) << 1);
    const int brow = ((lane & 15)) * APB + (((lane >> 4) << 3) << 1);

    for (int kt = 0; kt <= qt; kt++) {
        __syncthreads();                     // prev tile's reads done
        // ---- stage K,V tiles (hi|lo) ----
        const size_t koff = (size_t)kt * 128 * 256;
#pragma unroll
        for (int x = 0; x < 16; x++) {
            int idx = tid + x * 256;
            int r = idx >> 5, sub = idx & 31;
            int pl = sub >> 4, cc = sub & 15;
            const char* src = (pl ? Klb : Khb) + koff + (size_t)r * 256 + cc * 16;
            CP16(Ks + r * APB + pl * 256 + cc * 16, src);
        }
#pragma unroll
        for (int x = 0; x < 16; x++) {
            int idx = tid + x * 256;
            int r = idx >> 5, sub = idx & 31;
            int pl = sub >> 4, cc = sub & 15;
            const char* src = (pl ? Vlb : Vhb) + koff + (size_t)r * 256 + cc * 16;
            CP16(Vs + r * APB + pl * 256 + cc * 16, src);
        }
        CP_COMMIT();
        CP_WAIT0();
        __syncthreads();

        // ---- S = Qh*Kh + Qh*Kl + Ql*Kh ----
        float c[16][4];
#pragma unroll
        for (int nf = 0; nf < 16; nf++)
#pragma unroll
            for (int e = 0; e < 4; e++) c[nf][e] = 0.0f;

#pragma unroll
        for (int pass = 0; pass < 3; pass++) {
            const int aoff = (pass == 2) ? 256 : 0;       // bytes: lo plane at +256
            const int boff = (pass == 1) ? 256 : 0;
#pragma unroll
            for (int s = 0; s < 8; s++) {
                uint32_t af[4];
                LDMX4(af[0], af[1], af[2], af[3], Qs + arow + aoff + s * 32);
#pragma unroll
                for (int f = 0; f < 8; f++) {
                    uint32_t r0, r1, r2, r3;
                    LDMX4(r0, r1, r2, r3, Ks + f * 16 * APB + brow + boff + s * 32);
                    uint32_t be[2] = {r0, r2}, bo[2] = {r1, r3};
                    MMA16816(c[2 * f],     af, be);
                    MMA16816(c[2 * f + 1], af, bo);
                }
            }
        }

        // ---- mask (diagonal tile) + online softmax + pack P ----
        if (kt == qt) {
            const int rbase = wid * 16 + (lane >> 2);
            const int cbase = (lane & 3) * 2;
#pragma unroll
            for (int nf = 0; nf < 16; nf++) {
#pragma unroll
                for (int e = 0; e < 4; e++) {
                    int colL = nf * 8 + cbase + (e & 1);
                    int rowL = rbase + (e >> 1) * 8;
                    if (colL > rowL) c[nf][e] = -1e30f;
                }
            }
        }

        uint32_t Ph[32], Pl[32];
#pragma unroll
        for (int rh = 0; rh < 2; rh++) {
            float rm = -1e30f;
#pragma unroll
            for (int nf = 0; nf < 16; nf++)
                rm = fmaxf(rm, fmaxf(c[nf][rh * 2], c[nf][rh * 2 + 1]));
            rm = fmaxf(rm, __shfl_xor_sync(0xffffffffu, rm, 1));
            rm = fmaxf(rm, __shfl_xor_sync(0xffffffffu, rm, 2));
            float mn    = fmaxf(m_i[rh], rm);
            float alpha = __expf(m_i[rh] - mn);
            m_i[rh] = mn;
            float rs = 0.0f;
#pragma unroll
            for (int nf = 0; nf < 16; nf++) {
                float p0 = __expf(c[nf][rh * 2]     - mn);
                float p1 = __expf(c[nf][rh * 2 + 1] - mn);
                rs += p0 + p1;
                __nv_bfloat16 h0 = __float2bfloat16_rn(p0);
                __nv_bfloat16 h1 = __float2bfloat16_rn(p1);
                Ph[nf * 2 + rh] = pack_bf16x2(__bfloat162float(h0), __bfloat162float(h1));
                Pl[nf * 2 + rh] = pack_bf16x2(p0 - __bfloat162float(h0),
                                              p1 - __bfloat162float(h1));
            }
            rs += __shfl_xor_sync(0xffffffffu, rs, 1);
            rs += __shfl_xor_sync(0xffffffffu, rs, 2);
            l_i[rh] = l_i[rh] * alpha + rs;
#pragma unroll
            for (int nf = 0; nf < 16; nf++) {
                O[nf][rh * 2]     *= alpha;
                O[nf][rh * 2 + 1] *= alpha;
            }
        }

        // ---- O += Ph*Vh + Ph*Vl + Pl*Vh ----
#pragma unroll
        for (int pass = 0; pass < 3; pass++) {
            const uint32_t* P = (pass == 2) ? Pl : Ph;
            const int voff = (pass == 1) ? 256 : 0;       // Vl plane bytes
#pragma unroll
            for (int s = 0; s < 8; s++) {
                uint32_t af[4] = {P[(2 * s) * 2 + 0], P[(2 * s) * 2 + 1],
                                  P[(2 * s + 1) * 2 + 0], P[(2 * s + 1) * 2 + 1]};
#pragma unroll
                for (int f = 0; f < 8; f++) {
                    uint32_t m0, m1, m2, m3;
                    LDMX4T(m0, m1, m2, m3,
                           Vs + (s * 16 + (lane & 15)) * APB + voff
                              + ((f * 16 + ((lane >> 4) << 3)) << 1));
                    uint32_t be[2] = {m0, m1}, bo[2] = {m2, m3};
                    MMA16816(O[2 * f],     af, be);
                    MMA16816(O[2 * f + 1], af, bo);
                }
            }
        }
    }

    // ---- epilogue: normalize, split hi/lo, write bf16x3 rows of g_ao ----
    const int rbase = wid * 16 + (lane >> 2);
    const int cbase = (lane & 3) * 2;
#pragma unroll
    for (int rh = 0; rh < 2; rh++) {
        float inv = 1.0f / l_i[rh];
        int t = qt * 128 + rbase + rh * 8;
        size_t gm = (size_t)b * T_SZ + t;
        __nv_bfloat16* rowp = Ao + gm * KP + h * HD;
#pragma unroll
        for (int nf = 0; nf < 16; nf++) {
            float o0 = O[nf][rh * 2]     * inv;
            float o1 = O[nf][rh * 2 + 1] * inv;
            __nv_bfloat16 h0 = __float2bfloat16_rn(o0);
            __nv_bfloat16 h1 = __float2bfloat16_rn(o1);
            uint32_t hi = pack_bf16x2(__bfloat162float(h0), __bfloat162float(h1));
            uint32_t lo = pack_bf16x2(o0 - __bfloat162float(h0), o1 - __bfloat162float(h1));
            int k = nf * 8 + cbase;
            *(uint32_t*)(rowp + k)           = hi;
            *(uint32_t*)(rowp + DIM + k)     = hi;
            *(uint32_t*)(rowp + 2 * DIM + k) = lo;
        }
    }
}

// ---------------------------------------------------------------------------
// kernel_launch
// ---------------------------------------------------------------------------
extern "C" void kernel_launch(void* const* d_in, const int* in_sizes, int n_in,
                              void* d_out, int out_size)
{
    (void)in_sizes; (void)n_in; (void)out_size;
    const float* hidden = (const float*)d_in[0];
    const float* cosb   = (const float*)d_in[1];
    const float* sinb   = (const float*)d_in[2];
    const float* wq     = (const float*)d_in[3];
    const float* wk     = (const float*)d_in[4];
    const float* wv     = (const float*)d_in[5];
    const float* wo     = (const float*)d_in[6];
    float* out = (float*)d_out;

    float *gq, *gk, *gv;
    __nv_bfloat16 *gah, *gwqkv, *gao, *gwoh;
    __nv_bfloat16 *gqh, *gql, *gkh, *gkl, *gvh, *gvl;
    cudaGetSymbolAddress((void**)&gq,    g_q);
    cudaGetSymbolAddress((void**)&gk,    g_k);
    cudaGetSymbolAddress((void**)&gv,    g_v);
    cudaGetSymbolAddress((void**)&gah,   g_ah);
    cudaGetSymbolAddress((void**)&gwqkv, g_wqkv);
    cudaGetSymbolAddress((void**)&gao,   g_ao);
    cudaGetSymbolAddress((void**)&gwoh,  g_woh);
    cudaGetSymbolAddress((void**)&gqh,   g_qh);
    cudaGetSymbolAddress((void**)&gql,   g_ql);
    cudaGetSymbolAddress((void**)&gkh,   g_kh);
    cudaGetSymbolAddress((void**)&gkl,   g_kl);
    cudaGetSymbolAddress((void**)&gvh,   g_vh);
    cudaGetSymbolAddress((void**)&gvl,   g_vl);

    cudaFuncSetAttribute(gemm_mma_bf16x3, cudaFuncAttributeMaxDynamicSharedMemorySize, GEMM_SMEM);
    cudaFuncSetAttribute(attn_mma, cudaFuncAttributeMaxDynamicSharedMemorySize, ATT_SMEM);

    // --- bf16x3 conversions ---
    convert_split<<<MTOT * DIM / 4 / 256, 256>>>(hidden, gah, 0);
    convert_split<<<2048 * DIM / 4 / 256, 256>>>(wq, gwqkv, 1);
    convert_split<<< 512 * DIM / 4 / 256, 256>>>(wk, gwqkv + (size_t)2048 * KP, 1);
    convert_split<<< 512 * DIM / 4 / 256, 256>>>(wv, gwqkv + (size_t)2560 * KP, 1);
    convert_split<<<2048 * DIM / 4 / 256, 256>>>(wo, gwoh, 1);

    // --- fused QKV projection (mma.sync bf16x3), scatter epilogue ---
    gemm_mma_bf16x3<<<dim3(3072 / BN, MTOT / BM), 256, GEMM_SMEM>>>(
        gah, gwqkv, gq, gk, gv, 1, 0);

    // --- RoPE + split (scale folded into Q); V split ---
    const float scale = 0.088388347648318447f;   // 1/sqrt(128)
    rope_split<<<B_SZ * NH  * T_SZ / 4, 256>>>(gq, cosb, sinb, gqh, gql, NH,  scale);
    rope_split<<<B_SZ * NKV * T_SZ / 4, 256>>>(gk, cosb, sinb, gkh, gkl, NKV, 1.0f);
    split_hl<<<(B_SZ * NKV * T_SZ * HD) / 4 / 256, 256>>>(gv, gvh, gvl);

    // --- Flash attention (mma.sync, causal, GQA) -> writes g_ao bf16x3 ---
    attn_mma<<<dim3(T_SZ / 128, NH, B_SZ), 256, ATT_SMEM>>>(
        gqh, gql, gkh, gkl, gvh, gvl, gao);

    // --- wo projection ---
    gemm_mma_bf16x3<<<dim3(DIM / BN, MTOT / BM), 256, GEMM_SMEM>>>(
        gao, gwoh, out, nullptr, nullptr, 0, DIM);
}